// round 13
// baseline (speedup 1.0000x reference)
#include <cuda_runtime.h>
#include <cstdint>

#define BB 8
#define HH 180
#define WW 180
#define NF 24
#define NB 31
#define NLUT 4096
#define PIX (HH*WW)
#define NPIX (BB*PIX)
#define PW 184
#define FPB 8                   // filters per block (3-way split)

typedef unsigned long long ull;

// ---------------- device globals ----------------
__device__ float2 d_lut[NLUT];
__device__ float2 d_fA[NF*30];
__device__ float2 d_fB[NF*30];
__device__ float  d_Msum;
__device__ float  d_part[3][BB*HH*PW];

// ---------------- f32x2 helpers ----------------
__device__ __forceinline__ ull fma2(ull a, ull b, ull c) {
    ull d;
    asm("fma.rn.f32x2 %0, %1, %2, %3;" : "=l"(d) : "l"(a), "l"(b), "l"(c));
    return d;
}
__device__ __forceinline__ ull pack2(float lo, float hi) {
    ull r;
    asm("mov.b64 %0, {%1, %2};" : "=l"(r) : "f"(lo), "f"(hi));
    return r;
}
__device__ __forceinline__ void unpack2(ull v, float& lo, float& hi) {
    asm("mov.b64 {%0, %1}, %2;" : "=f"(lo), "=f"(hi) : "l"(v));
}

__device__ __forceinline__ float lutphi(float x) {
    float t = fmaf(x, 1024.0f, 2048.0f);
    t = fminf(fmaxf(t, 0.0f), 4095.5f);
    int ii = (int)t;
    float fr = t - (float)ii;
    float2 L = __ldg(&d_lut[ii]);
    return fmaf(fr, L.y, L.x);
}

__device__ __forceinline__ float rbf_partial(float x, int r,
                                             const float* mu, const float* w) {
    float y = 0.0f;
    #pragma unroll 1
    for (int j = r; j < NB; j += 4) {
        float t = x - __ldg(&mu[j]);
        y += __ldg(&w[j]) * __expf(-50.0f * t * t);
    }
    return y;
}

// ---------------- K0: prep (R10 shape) ----------------
__global__ void k_pre(const float* __restrict__ filters,
                      const float* __restrict__ mu,
                      const float* __restrict__ weights) {
    const int blk = blockIdx.x, tid = threadIdx.x;
    if (blk == 0 && tid == 0) d_Msum = 0.0f;
    if (blk < 64) {
        __shared__ float sy[65];
        const float h = 4.0f / (float)NLUT;
        const int el = tid >> 2;
        const int r = tid & 3;
        const int entry = blk * 64 + el;
        float x = fmaf((float)entry, h, -2.0f);
        float p = rbf_partial(x, r, mu, weights);
        p += __shfl_xor_sync(0xFFFFFFFFu, p, 1);
        p += __shfl_xor_sync(0xFFFFFFFFu, p, 2);
        if (r == 0) sy[el] = p;
        if (tid < 4) {
            float xb = fmaf((float)(blk * 64 + 64), h, -2.0f);
            float pb = rbf_partial(xb, tid, mu, weights);
            pb += __shfl_xor_sync(0xFu, pb, 1);
            pb += __shfl_xor_sync(0xFu, pb, 2);
            if (tid == 0) sy[64] = pb;
        }
        __syncthreads();
        if (tid < 64) {
            int e = blk * 64 + tid;
            d_lut[e] = make_float2(sy[tid], sy[tid + 1] - sy[tid]);
        }
    } else {
        int t = (blk - 64) * 256 + tid;
        if (t < NF * 30) {
            int f = t / 30, e = t % 30;
            int rr = e / 6, c = e % 6;
            float wA = 0.0f, wB = 0.0f;
            if (c < 5) {
                wA = __ldg(&filters[f * 25 + rr * 5 + c]);
                wB = __ldg(&filters[f * 25 + (4 - rr) * 5 + (4 - c)]);
            }
            d_fA[t] = make_float2(wA, wA);
            d_fB[t] = make_float2(wB, wB);
        }
    }
}

// ---------------- conv building blocks ----------------
#define CONV5(a0, a1, C, E0, O0, E1, O1, E2, O2, E3)                         \
    do {                                                                     \
        a0 = fma2((C)[0], E0, a0); a0 = fma2((C)[1], O0, a0);                \
        a0 = fma2((C)[2], E1, a0); a0 = fma2((C)[3], O1, a0);                \
        a0 = fma2((C)[4], E2, a0);                                           \
        a1 = fma2((C)[0], E1, a1); a1 = fma2((C)[1], O1, a1);                \
        a1 = fma2((C)[2], E2, a1); a1 = fma2((C)[3], O2, a1);                \
        a1 = fma2((C)[4], E3, a1);                                           \
    } while (0)

#define LOADROW(base)                                                        \
    const ulonglong2* rp_ = (const ulonglong2*)(base);                       \
    ulonglong2 ra_ = rp_[0], rb_ = rp_[1];                                   \
    ull E0 = ra_.x, E1 = ra_.y, E2 = rb_.x, E3 = rb_.y;                      \
    float v0, v1, v2, v3, v4, v5, v6, v7;                                    \
    unpack2(E0, v0, v1); unpack2(E1, v2, v3);                                \
    unpack2(E2, v4, v5); unpack2(E3, v6, v7);                                \
    ull O0 = pack2(v1, v2), O1 = pack2(v3, v4), O2 = pack2(v5, v6);          \
    (void)v0; (void)v7;

#define LOADCOEF(cf, k, cc)                                                  \
    do {                                                                     \
        const ulonglong2* cv_ = (const ulonglong2*)((cf) + (k) * 6);         \
        ulonglong2 x0_ = cv_[0], x1_ = cv_[1];                               \
        cc[0] = x0_.x; cc[1] = x0_.y; cc[2] = x1_.x; cc[3] = x1_.y;          \
        cc[4] = *(const ull*)((cf) + (k) * 6 + 4);                           \
    } while (0)

__device__ __forceinline__ void stageA(const float* __restrict__ su,
                                       const float2* __restrict__ cf,
                                       float* __restrict__ bw,
                                       int p0, int q0,
                                       const float us0[4], const float us1[4],
                                       const float us2[4]) {
    ull A0 = 0, B0 = 0, A1 = 0, B1 = 0, A2 = 0, B2 = 0;
    ull cc[5], cp[5], cq[5];
    #pragma unroll
    for (int k = 0; k < 7; k++) {
        LOADROW(su + (p0 + k) * 40 + q0);
        if (k <= 4) {
            LOADCOEF(cf, k, cc);
            CONV5(A0, B0, cc, E0, O0, E1, O1, E2, O2, E3);
        }
        if (k >= 1 && k <= 5) CONV5(A1, B1, cp, E0, O0, E1, O1, E2, O2, E3);
        if (k >= 2)           CONV5(A2, B2, cq, E0, O0, E1, O1, E2, O2, E3);
        #pragma unroll
        for (int t = 0; t < 5; t++) { cq[t] = cp[t]; cp[t] = cc[t]; }
    }
    float c0, c1, c2, c3;
    float4 res;
    unpack2(A0, c0, c1); unpack2(B0, c2, c3);
    res.x = lutphi(c0) * us0[0]; res.y = lutphi(c1) * us0[1];
    res.z = lutphi(c2) * us0[2]; res.w = lutphi(c3) * us0[3];
    *(float4*)(bw + p0 * 40 + q0) = res;
    unpack2(A1, c0, c1); unpack2(B1, c2, c3);
    res.x = lutphi(c0) * us1[0]; res.y = lutphi(c1) * us1[1];
    res.z = lutphi(c2) * us1[2]; res.w = lutphi(c3) * us1[3];
    *(float4*)(bw + (p0 + 1) * 40 + q0) = res;
    unpack2(A2, c0, c1); unpack2(B2, c2, c3);
    res.x = lutphi(c0) * us2[0]; res.y = lutphi(c1) * us2[1];
    res.z = lutphi(c2) * us2[2]; res.w = lutphi(c3) * us2[3];
    *(float4*)(bw + (p0 + 2) * 40 + q0) = res;
}

__device__ __forceinline__ void stageB(const float* __restrict__ bw,
                                       const float2* __restrict__ cf,
                                       int oy0, int ox0,
                                       ull& d0A, ull& d0B, ull& d1A, ull& d1B) {
    ull cc[5], cp[5];
    #pragma unroll
    for (int k = 0; k < 6; k++) {
        LOADROW(bw + (oy0 + k) * 40 + ox0);
        if (k <= 4) {
            LOADCOEF(cf, k, cc);
            CONV5(d0A, d0B, cc, E0, O0, E1, O1, E2, O2, E3);
        }
        if (k >= 1) CONV5(d1A, d1B, cp, E0, O0, E1, O1, E2, O2, E3);
        #pragma unroll
        for (int t = 0; t < 5; t++) cp[t] = cc[t];
    }
}

// ---------------- fused kernel: warp-specialized producer/consumer ----------------
__global__ __launch_bounds__(256, 3) void k_fused(const float* __restrict__ u) {
    __shared__ __align__(16) float su[40 * 40];
    __shared__ __align__(16) float bufs[4][36 * 40];
    __shared__ __align__(16) float2 sfa[FPB * 30];
    __shared__ __align__(16) float2 sfb[FPB * 30];

    const int tid = threadIdx.x;
    const int group = tid >> 7;          // 0 = producer (stageA), 1 = consumer (stageB)
    const int wt = tid & 127;
    const int third = blockIdx.z % 3;
    const int b = blockIdx.z / 3;
    const int f0 = third * FPB;
    const int gx0 = blockIdx.x * 30;
    const int gy0 = blockIdx.y * 30;

    for (int i = tid; i < FPB * 30; i += 256) {
        sfa[i] = d_fA[f0 * 30 + i];
        sfb[i] = d_fB[f0 * 30 + i];
    }

    const float* ub = u + b * PIX;
    for (int i = tid; i < 1600; i += 256) {
        int r = i / 40, c = i % 40;
        int gy = gy0 - 4 + r, gx = gx0 - 4 + c;
        float v = 0.0f;
        if (gy >= 0 && gy < HH && gx >= 0 && gx < WW) v = __ldg(&ub[gy * WW + gx]);
        su[i] = v;
    }
    __syncthreads();

    const int p0 = (wt / 9) * 3;
    const int q0 = (wt % 9) * 4;
    const int oy0 = (wt >> 3) * 2;
    const int ox0 = (wt & 7) * 4;

    // tile-local M reduction on warps 0-3 only (full warps in shuffle)
    if (third == 0 && tid < 128) {
        float s = 0.0f;
        if (tid < 120) {
            #pragma unroll
            for (int i = 0; i < 2; i++) {
                int gy = gy0 + oy0 + i;
                float wy = (gy == 0 || gy == HH - 1) ? 2.0f : 3.0f;
                #pragma unroll
                for (int j = 0; j < 4; j++) {
                    int ox = ox0 + j;
                    if (ox < 30) {
                        int gx = gx0 + ox;
                        float wx = (gx == 0 || gx == WW - 1) ? 2.0f : 3.0f;
                        s += su[(oy0 + i + 4) * 40 + (ox + 4)] * wy * wx;
                    }
                }
            }
        }
        #pragma unroll
        for (int o = 16; o > 0; o >>= 1) s += __shfl_xor_sync(0xFFFFFFFFu, s, o);
        if ((tid & 31) == 0) atomicAdd(&d_Msum, s);
    }

    // hoisted boxsum (producers only)
    float us0[4] = {0, 0, 0, 0}, us1[4] = {0, 0, 0, 0}, us2[4] = {0, 0, 0, 0};
    if (group == 0 && wt < 108) {
        #pragma unroll
        for (int k = 1; k <= 5; k++) {
            const float4* rp = (const float4*)(su + (p0 + k) * 40 + q0);
            float4 a = rp[0], bq = rp[1];
            float a_ = a.z + a.w, b_ = bq.x + bq.y;
            float hs0 = a.y + a_, hs1 = a_ + bq.x, hs2 = a.w + b_, hs3 = b_ + bq.z;
            if (k <= 3)           { us0[0] += hs0; us0[1] += hs1; us0[2] += hs2; us0[3] += hs3; }
            if (k >= 2 && k <= 4) { us1[0] += hs0; us1[1] += hs1; us1[2] += hs2; us1[3] += hs3; }
            if (k >= 3)           { us2[0] += hs0; us2[1] += hs1; us2[2] += hs2; us2[3] += hs3; }
        }
        #pragma unroll
        for (int j = 0; j < 4; j++) {
            int gx = gx0 - 2 + q0 + j;
            float cm = (gx >= 0 && gx < WW) ? 1.0f : 0.0f;
            int g0 = gy0 - 2 + p0;
            us0[j] *= cm * ((g0 >= 0 && g0 < HH) ? 1.0f : 0.0f);
            us1[j] *= cm * ((g0 + 1 >= 0 && g0 + 1 < HH) ? 1.0f : 0.0f);
            us2[j] *= cm * ((g0 + 2 >= 0 && g0 + 2 < HH) ? 1.0f : 0.0f);
        }
    }

    ull d0A = 0, d0B = 0, d1A = 0, d1B = 0;

    // software pipeline: producers fill bufs{2g&3,2g+1&3} while consumers
    // drain bufs{(2g-2)&3,(2g-1)&3} — disjoint pairs, one barrier per step.
    #pragma unroll 1
    for (int g = 0; g < FPB / 2 + 1; g++) {
        if (group == 0 && g < FPB / 2 && wt < 108) {
            const int fa = 2 * g, fb = 2 * g + 1;
            stageA(su, &sfa[fa * 30], bufs[fa & 3], p0, q0, us0, us1, us2);
            stageA(su, &sfa[fb * 30], bufs[fb & 3], p0, q0, us0, us1, us2);
        }
        if (group == 1 && g >= 1 && wt < 120) {
            const int fa = 2 * g - 2, fb = 2 * g - 1;
            stageB(bufs[fa & 3], &sfb[fa * 30], oy0, ox0, d0A, d0B, d1A, d1B);
            stageB(bufs[fb & 3], &sfb[fb * 30], oy0, ox0, d0A, d0B, d1A, d1B);
        }
        __syncthreads();
    }

    if (group == 1 && wt < 120) {
        float a0, a1, b0, b1;
        float* pp = &d_part[third][(b * HH + gy0 + oy0) * PW + gx0 + ox0];
        unpack2(d0A, a0, a1); unpack2(d0B, b0, b1);
        *(float2*)pp = make_float2(a0, a1);
        if (ox0 < 28) *(float2*)(pp + 2) = make_float2(b0, b1);
        pp += PW;
        unpack2(d1A, a0, a1); unpack2(d1B, b0, b1);
        *(float2*)pp = make_float2(a0, a1);
        if (ox0 < 28) *(float2*)(pp + 2) = make_float2(b0, b1);
    }
}

// ---------------- combine ----------------
__global__ void k_combine(const float* __restrict__ u,
                          const float* __restrict__ fin,
                          const float* __restrict__ lam,
                          float* __restrict__ out) {
    __shared__ float sv[2];
    if (threadIdx.x == 0) {
        float M = d_Msum * (1.0f / (9.0f * (float)NPIX)) + 0.001f;
        sv[0] = 1.0f / (9.0f * M);
        sv[1] = __ldg(lam);
    }
    __syncthreads();
    const float sc = sv[0], lamv = sv[1];
    const int NG = BB * HH * 45;
    for (int g = blockIdx.x * blockDim.x + threadIdx.x; g < NG;
         g += gridDim.x * blockDim.x) {
        int b = g / (HH * 45);
        int r = g - b * (HH * 45);
        int gy = r / 45;
        int gx = (r - gy * 45) * 4;
        int idx = b * PIX + gy * WW + gx;
        int pidx = (b * HH + gy) * PW + gx;
        float4 uu = *(const float4*)(u + idx);
        float4 ff = *(const float4*)(fin + idx);
        float4 p0 = *(const float4*)(&d_part[0][pidx]);
        float4 p1 = *(const float4*)(&d_part[1][pidx]);
        float4 p2 = *(const float4*)(&d_part[2][pidx]);
        float4 o;
        o.x = fminf(fmaxf(uu.x - (p0.x + p1.x + p2.x) * sc - lamv * (uu.x - ff.x) / (uu.x * uu.x + 1e-3f), 0.0f), 1.0f);
        o.y = fminf(fmaxf(uu.y - (p0.y + p1.y + p2.y) * sc - lamv * (uu.y - ff.y) / (uu.y * uu.y + 1e-3f), 0.0f), 1.0f);
        o.z = fminf(fmaxf(uu.z - (p0.z + p1.z + p2.z) * sc - lamv * (uu.z - ff.z) / (uu.z * uu.z + 1e-3f), 0.0f), 1.0f);
        o.w = fminf(fmaxf(uu.w - (p0.w + p1.w + p2.w) * sc - lamv * (uu.w - ff.w) / (uu.w * uu.w + 1e-3f), 0.0f), 1.0f);
        *(float4*)(out + idx) = o;
    }
}

// ---------------- launch ----------------
extern "C" void kernel_launch(void* const* d_in, const int* in_sizes, int n_in,
                              void* d_out, int out_size) {
    const float* u       = (const float*)d_in[0];
    const float* f       = (const float*)d_in[1];
    const float* filters = (const float*)d_in[2];
    const float* lam     = (const float*)d_in[3];
    const float* mu      = (const float*)d_in[4];
    const float* weights = (const float*)d_in[5];
    float* out = (float*)d_out;

    k_pre<<<67, 256>>>(filters, mu, weights);

    dim3 grid(WW / 30, HH / 30, BB * 3);   // 864 blocks
    k_fused<<<grid, 256>>>(u);

    k_combine<<<128, 256>>>(u, f, lam, out);
}

// round 16
// speedup vs baseline: 1.1628x; 1.1628x over previous
#include <cuda_runtime.h>
#include <cstdint>

#define BB 8
#define HH 180
#define WW 180
#define NF 24
#define NB 31
#define NLUT 4096
#define PIX (HH*WW)
#define NPIX (BB*PIX)
#define PW 184
#define FPB 8                   // filters per block (3-way split)

typedef unsigned long long ull;

// ---------------- device globals ----------------
__device__ float2 d_lut[NLUT];
__device__ float2 d_fA[NF*30];
__device__ float2 d_fB[NF*30];
__device__ float  d_Msum;
__device__ float  d_part[3][BB*HH*PW];

// ---------------- f32x2 helpers ----------------
__device__ __forceinline__ ull fma2(ull a, ull b, ull c) {
    ull d;
    asm("fma.rn.f32x2 %0, %1, %2, %3;" : "=l"(d) : "l"(a), "l"(b), "l"(c));
    return d;
}
__device__ __forceinline__ ull pack2(float lo, float hi) {
    ull r;
    asm("mov.b64 %0, {%1, %2};" : "=l"(r) : "f"(lo), "f"(hi));
    return r;
}
__device__ __forceinline__ void unpack2(ull v, float& lo, float& hi) {
    asm("mov.b64 {%0, %1}, %2;" : "=f"(lo), "=f"(hi) : "l"(v));
}

__device__ __forceinline__ float lutphi(float x) {
    float t = fmaf(x, 1024.0f, 2048.0f);
    t = fminf(fmaxf(t, 0.0f), 4095.5f);
    int ii = (int)t;
    float fr = t - (float)ii;
    float2 L = __ldg(&d_lut[ii]);
    return fmaf(fr, L.y, L.x);
}

// ---------------- K0: prep — smem-hoisted RBF params (kills serial LDG chain) ----------------
__global__ void k_pre(const float* __restrict__ filters,
                      const float* __restrict__ mu,
                      const float* __restrict__ weights) {
    const int blk = blockIdx.x, tid = threadIdx.x;
    if (blk == 0 && tid == 0) d_Msum = 0.0f;
    if (blk < 64) {
        __shared__ float sm[NB], sw[NB];
        __shared__ float sy[65];
        if (tid < NB) {
            sm[tid] = __ldg(&mu[tid]);
            sw[tid] = __ldg(&weights[tid]);
        }
        __syncthreads();
        if (tid < 65) {
            const float h = 4.0f / (float)NLUT;
            float x = fmaf((float)(blk * 64 + tid), h, -2.0f);
            float y = 0.0f;
            #pragma unroll
            for (int j = 0; j < NB; j++) {
                float t = x - sm[j];
                y += sw[j] * __expf(-50.0f * t * t);
            }
            sy[tid] = y;
        }
        __syncthreads();
        if (tid < 64) {
            int e = blk * 64 + tid;
            d_lut[e] = make_float2(sy[tid], sy[tid + 1] - sy[tid]);
        }
    } else {
        int t = (blk - 64) * 256 + tid;
        if (t < NF * 30) {
            int f = t / 30, e = t % 30;
            int rr = e / 6, c = e % 6;
            float wA = 0.0f, wB = 0.0f;
            if (c < 5) {
                wA = __ldg(&filters[f * 25 + rr * 5 + c]);
                wB = __ldg(&filters[f * 25 + (4 - rr) * 5 + (4 - c)]);
            }
            d_fA[t] = make_float2(wA, wA);
            d_fB[t] = make_float2(wB, wB);
        }
    }
}

// ---------------- conv building blocks ----------------
#define CONV5(a0, a1, C, E0, O0, E1, O1, E2, O2, E3)                         \
    do {                                                                     \
        a0 = fma2((C)[0], E0, a0); a0 = fma2((C)[1], O0, a0);                \
        a0 = fma2((C)[2], E1, a0); a0 = fma2((C)[3], O1, a0);                \
        a0 = fma2((C)[4], E2, a0);                                           \
        a1 = fma2((C)[0], E1, a1); a1 = fma2((C)[1], O1, a1);                \
        a1 = fma2((C)[2], E2, a1); a1 = fma2((C)[3], O2, a1);                \
        a1 = fma2((C)[4], E3, a1);                                           \
    } while (0)

#define LOADROW(base)                                                        \
    const ulonglong2* rp_ = (const ulonglong2*)(base);                       \
    ulonglong2 ra_ = rp_[0], rb_ = rp_[1];                                   \
    ull E0 = ra_.x, E1 = ra_.y, E2 = rb_.x, E3 = rb_.y;                      \
    float v0, v1, v2, v3, v4, v5, v6, v7;                                    \
    unpack2(E0, v0, v1); unpack2(E1, v2, v3);                                \
    unpack2(E2, v4, v5); unpack2(E3, v6, v7);                                \
    ull O0 = pack2(v1, v2), O1 = pack2(v3, v4), O2 = pack2(v5, v6);          \
    (void)v0; (void)v7;

#define LOADCOEF(cf, k, cc)                                                  \
    do {                                                                     \
        const ulonglong2* cv_ = (const ulonglong2*)((cf) + (k) * 6);         \
        ulonglong2 x0_ = cv_[0], x1_ = cv_[1];                               \
        cc[0] = x0_.x; cc[1] = x0_.y; cc[2] = x1_.x; cc[3] = x1_.y;          \
        cc[4] = *(const ull*)((cf) + (k) * 6 + 4);                           \
    } while (0)

__device__ __forceinline__ void stageA(const float* __restrict__ su,
                                       const float2* __restrict__ cf,
                                       float* __restrict__ bw,
                                       int p0, int q0,
                                       const float us0[4], const float us1[4],
                                       const float us2[4]) {
    ull A0 = 0, B0 = 0, A1 = 0, B1 = 0, A2 = 0, B2 = 0;
    ull cc[5], cp[5], cq[5];
    #pragma unroll
    for (int k = 0; k < 7; k++) {
        LOADROW(su + (p0 + k) * 40 + q0);
        if (k <= 4) {
            LOADCOEF(cf, k, cc);
            CONV5(A0, B0, cc, E0, O0, E1, O1, E2, O2, E3);
        }
        if (k >= 1 && k <= 5) CONV5(A1, B1, cp, E0, O0, E1, O1, E2, O2, E3);
        if (k >= 2)           CONV5(A2, B2, cq, E0, O0, E1, O1, E2, O2, E3);
        #pragma unroll
        for (int t = 0; t < 5; t++) { cq[t] = cp[t]; cp[t] = cc[t]; }
    }
    float c0, c1, c2, c3;
    float4 res;
    unpack2(A0, c0, c1); unpack2(B0, c2, c3);
    res.x = lutphi(c0) * us0[0]; res.y = lutphi(c1) * us0[1];
    res.z = lutphi(c2) * us0[2]; res.w = lutphi(c3) * us0[3];
    *(float4*)(bw + p0 * 40 + q0) = res;
    unpack2(A1, c0, c1); unpack2(B1, c2, c3);
    res.x = lutphi(c0) * us1[0]; res.y = lutphi(c1) * us1[1];
    res.z = lutphi(c2) * us1[2]; res.w = lutphi(c3) * us1[3];
    *(float4*)(bw + (p0 + 1) * 40 + q0) = res;
    unpack2(A2, c0, c1); unpack2(B2, c2, c3);
    res.x = lutphi(c0) * us2[0]; res.y = lutphi(c1) * us2[1];
    res.z = lutphi(c2) * us2[2]; res.w = lutphi(c3) * us2[3];
    *(float4*)(bw + (p0 + 2) * 40 + q0) = res;
}

__device__ __forceinline__ void stageB(const float* __restrict__ bw,
                                       const float2* __restrict__ cf,
                                       int oy0, int ox0,
                                       ull& d0A, ull& d0B, ull& d1A, ull& d1B) {
    ull cc[5], cp[5];
    #pragma unroll
    for (int k = 0; k < 6; k++) {
        LOADROW(bw + (oy0 + k) * 40 + ox0);
        if (k <= 4) {
            LOADCOEF(cf, k, cc);
            CONV5(d0A, d0B, cc, E0, O0, E1, O1, E2, O2, E3);
        }
        if (k >= 1) CONV5(d1A, d1B, cp, E0, O0, E1, O1, E2, O2, E3);
        #pragma unroll
        for (int t = 0; t < 5; t++) cp[t] = cc[t];
    }
}

// ---------------- fused kernel: 8 filters per block, 2 per phase (R10 config) ----------------
__global__ __launch_bounds__(128, 6) void k_fused(const float* __restrict__ u) {
    __shared__ __align__(16) float su[40 * 40];
    __shared__ __align__(16) float bufs[4][36 * 40];
    __shared__ __align__(16) float2 sfa[FPB * 30];
    __shared__ __align__(16) float2 sfb[FPB * 30];

    const int tid = threadIdx.x;
    const int third = blockIdx.z % 3;
    const int b = blockIdx.z / 3;
    const int f0 = third * FPB;
    const int gx0 = blockIdx.x * 30;
    const int gy0 = blockIdx.y * 30;

    for (int i = tid; i < FPB * 30; i += 128) {
        sfa[i] = d_fA[f0 * 30 + i];
        sfb[i] = d_fB[f0 * 30 + i];
    }

    const float* ub = u + b * PIX;
    for (int i = tid; i < 1600; i += 128) {
        int r = i / 40, c = i % 40;
        int gy = gy0 - 4 + r, gx = gx0 - 4 + c;
        float v = 0.0f;
        if (gy >= 0 && gy < HH && gx >= 0 && gx < WW) v = __ldg(&ub[gy * WW + gx]);
        su[i] = v;
    }
    __syncthreads();

    const int p0 = (tid / 9) * 3;
    const int q0 = (tid % 9) * 4;
    const int oy0 = (tid >> 3) * 2;
    const int ox0 = (tid & 7) * 4;

    // tile-local M reduction (third==0 only); full-warp shuffle masks
    if (third == 0) {
        float s = 0.0f;
        if (tid < 120) {
            #pragma unroll
            for (int i = 0; i < 2; i++) {
                int gy = gy0 + oy0 + i;
                float wy = (gy == 0 || gy == HH - 1) ? 2.0f : 3.0f;
                #pragma unroll
                for (int j = 0; j < 4; j++) {
                    int ox = ox0 + j;
                    if (ox < 30) {
                        int gx = gx0 + ox;
                        float wx = (gx == 0 || gx == WW - 1) ? 2.0f : 3.0f;
                        s += su[(oy0 + i + 4) * 40 + (ox + 4)] * wy * wx;
                    }
                }
            }
        }
        #pragma unroll
        for (int o = 16; o > 0; o >>= 1) s += __shfl_xor_sync(0xFFFFFFFFu, s, o);
        if ((tid & 31) == 0) atomicAdd(&d_Msum, s);
    }

    // hoisted boxsum with masks folded in
    float us0[4] = {0, 0, 0, 0}, us1[4] = {0, 0, 0, 0}, us2[4] = {0, 0, 0, 0};
    if (tid < 108) {
        #pragma unroll
        for (int k = 1; k <= 5; k++) {
            const float4* rp = (const float4*)(su + (p0 + k) * 40 + q0);
            float4 a = rp[0], bq = rp[1];
            float a_ = a.z + a.w, b_ = bq.x + bq.y;
            float hs0 = a.y + a_, hs1 = a_ + bq.x, hs2 = a.w + b_, hs3 = b_ + bq.z;
            if (k <= 3)           { us0[0] += hs0; us0[1] += hs1; us0[2] += hs2; us0[3] += hs3; }
            if (k >= 2 && k <= 4) { us1[0] += hs0; us1[1] += hs1; us1[2] += hs2; us1[3] += hs3; }
            if (k >= 3)           { us2[0] += hs0; us2[1] += hs1; us2[2] += hs2; us2[3] += hs3; }
        }
        #pragma unroll
        for (int j = 0; j < 4; j++) {
            int gx = gx0 - 2 + q0 + j;
            float cm = (gx >= 0 && gx < WW) ? 1.0f : 0.0f;
            int g0 = gy0 - 2 + p0;
            us0[j] *= cm * ((g0 >= 0 && g0 < HH) ? 1.0f : 0.0f);
            us1[j] *= cm * ((g0 + 1 >= 0 && g0 + 1 < HH) ? 1.0f : 0.0f);
            us2[j] *= cm * ((g0 + 2 >= 0 && g0 + 2 < HH) ? 1.0f : 0.0f);
        }
    }

    ull d0A = 0, d0B = 0, d1A = 0, d1B = 0;

    #pragma unroll 1
    for (int g = 0; g < FPB / 2; g++) {
        const int fa = 2 * g, fb = 2 * g + 1;
        float* bwA = bufs[fa & 3];
        float* bwB = bufs[fb & 3];

        if (tid < 108) {
            stageA(su, &sfa[fa * 30], bwA, p0, q0, us0, us1, us2);
            stageA(su, &sfa[fb * 30], bwB, p0, q0, us0, us1, us2);
        }
        __syncthreads();
        if (tid < 120) {
            stageB(bwA, &sfb[fa * 30], oy0, ox0, d0A, d0B, d1A, d1B);
            stageB(bwB, &sfb[fb * 30], oy0, ox0, d0A, d0B, d1A, d1B);
        }
        if (g < FPB / 2 - 1) __syncthreads();
    }

    if (tid < 120) {
        float a0, a1, b0, b1;
        float* pp = &d_part[third][(b * HH + gy0 + oy0) * PW + gx0 + ox0];
        unpack2(d0A, a0, a1); unpack2(d0B, b0, b1);
        *(float2*)pp = make_float2(a0, a1);
        if (ox0 < 28) *(float2*)(pp + 2) = make_float2(b0, b1);
        pp += PW;
        unpack2(d1A, a0, a1); unpack2(d1B, b0, b1);
        *(float2*)pp = make_float2(a0, a1);
        if (ox0 < 28) *(float2*)(pp + 2) = make_float2(b0, b1);
    }
}

// ---------------- combine ----------------
__global__ void k_combine(const float* __restrict__ u,
                          const float* __restrict__ fin,
                          const float* __restrict__ lam,
                          float* __restrict__ out) {
    __shared__ float sv[2];
    if (threadIdx.x == 0) {
        float M = d_Msum * (1.0f / (9.0f * (float)NPIX)) + 0.001f;
        sv[0] = 1.0f / (9.0f * M);
        sv[1] = __ldg(lam);
    }
    __syncthreads();
    const float sc = sv[0], lamv = sv[1];
    const int NG = BB * HH * 45;
    for (int g = blockIdx.x * blockDim.x + threadIdx.x; g < NG;
         g += gridDim.x * blockDim.x) {
        int b = g / (HH * 45);
        int r = g - b * (HH * 45);
        int gy = r / 45;
        int gx = (r - gy * 45) * 4;
        int idx = b * PIX + gy * WW + gx;
        int pidx = (b * HH + gy) * PW + gx;
        float4 uu = *(const float4*)(u + idx);
        float4 ff = *(const float4*)(fin + idx);
        float4 p0 = *(const float4*)(&d_part[0][pidx]);
        float4 p1 = *(const float4*)(&d_part[1][pidx]);
        float4 p2 = *(const float4*)(&d_part[2][pidx]);
        float4 o;
        o.x = fminf(fmaxf(uu.x - (p0.x + p1.x + p2.x) * sc - lamv * (uu.x - ff.x) / (uu.x * uu.x + 1e-3f), 0.0f), 1.0f);
        o.y = fminf(fmaxf(uu.y - (p0.y + p1.y + p2.y) * sc - lamv * (uu.y - ff.y) / (uu.y * uu.y + 1e-3f), 0.0f), 1.0f);
        o.z = fminf(fmaxf(uu.z - (p0.z + p1.z + p2.z) * sc - lamv * (uu.z - ff.z) / (uu.z * uu.z + 1e-3f), 0.0f), 1.0f);
        o.w = fminf(fmaxf(uu.w - (p0.w + p1.w + p2.w) * sc - lamv * (uu.w - ff.w) / (uu.w * uu.w + 1e-3f), 0.0f), 1.0f);
        *(float4*)(out + idx) = o;
    }
}

// ---------------- launch ----------------
extern "C" void kernel_launch(void* const* d_in, const int* in_sizes, int n_in,
                              void* d_out, int out_size) {
    const float* u       = (const float*)d_in[0];
    const float* f       = (const float*)d_in[1];
    const float* filters = (const float*)d_in[2];
    const float* lam     = (const float*)d_in[3];
    const float* mu      = (const float*)d_in[4];
    const float* weights = (const float*)d_in[5];
    float* out = (float*)d_out;

    k_pre<<<67, 256>>>(filters, mu, weights);

    dim3 grid(WW / 30, HH / 30, BB * 3);   // 864 blocks
    k_fused<<<grid, 128>>>(u);

    k_combine<<<128, 256>>>(u, f, lam, out);
}